// round 5
// baseline (speedup 1.0000x reference)
#include <cuda_runtime.h>
#include <cuda_bf16.h>
#include <math.h>
#include <float.h>

#define NROWS 200000
#define NBAGS 25000
#define DIM   690
#define NREL  53
#define KPAD  704      // DIM padded to multiple of 32
#define NPAD  64       // NREL padded
#define BM    128      // rows per block tile
#define KC    32       // k chunk
#define NCHUNK (KPAD / KC)   // 22
#define APITCH 40      // smem pitch (bf16): 80B rows -> LDSM conflict-free
#define BPITCH 40
#define WCAP  128      // shared weight slots per bag

// ---------------- scratch (device globals: allocation-free) ----------------
__device__ __align__(16) float g_P[(size_t)NROWS * NPAD];       // 51.2 MB
__device__ __align__(16) __nv_bfloat16 g_Bhi[NPAD * KPAD];
__device__ __align__(16) __nv_bfloat16 g_Blo[NPAD * KPAD];
__device__ float g_wglob[NROWS];                                // fallback for huge bags

// ---------------- K0: build bf16 hi/lo B = rel (padded, [n][k]) ------------
__global__ void k_prep(const float* __restrict__ rel) {
    int idx = blockIdx.x * blockDim.x + threadIdx.x;
    if (idx >= NPAD * KPAD) return;
    int n = idx / KPAD, k = idx % KPAD;
    float v = (n < NREL && k < DIM) ? rel[n * DIM + k] : 0.f;
    __nv_bfloat16 hi = __float2bfloat16(v);
    g_Bhi[idx] = hi;
    g_Blo[idx] = __float2bfloat16(v - __bfloat162float(hi));
}

// ---------------- K1: P = repre @ rel^T via bf16 hi/lo mma.sync ------------
__device__ __forceinline__ void mma_bf16(float* c, const unsigned* a, const unsigned* b) {
    asm volatile(
        "mma.sync.aligned.m16n8k16.row.col.f32.bf16.bf16.f32 "
        "{%0,%1,%2,%3}, {%4,%5,%6,%7}, {%8,%9}, {%0,%1,%2,%3};"
        : "+f"(c[0]), "+f"(c[1]), "+f"(c[2]), "+f"(c[3])
        : "r"(a[0]), "r"(a[1]), "r"(a[2]), "r"(a[3]), "r"(b[0]), "r"(b[1]));
}
__device__ __forceinline__ void ldsm4(unsigned* r, unsigned addr) {
    asm volatile("ldmatrix.sync.aligned.m8n8.x4.shared.b16 {%0,%1,%2,%3}, [%4];"
                 : "=r"(r[0]), "=r"(r[1]), "=r"(r[2]), "=r"(r[3]) : "r"(addr));
}
__device__ __forceinline__ void ldsm2(unsigned* r, unsigned addr) {
    asm volatile("ldmatrix.sync.aligned.m8n8.x2.shared.b16 {%0,%1}, [%2];"
                 : "=r"(r[0]), "=r"(r[1]) : "r"(addr));
}

__global__ __launch_bounds__(256) void k_pgemm(const float* __restrict__ repre) {
    __shared__ __align__(16) __nv_bfloat16 sAhi[BM * APITCH];
    __shared__ __align__(16) __nv_bfloat16 sAlo[BM * APITCH];
    __shared__ __align__(16) __nv_bfloat16 sBhi[NPAD * BPITCH];
    __shared__ __align__(16) __nv_bfloat16 sBlo[NPAD * BPITCH];

    int row0 = blockIdx.x * BM;
    int tid = threadIdx.x;
    int wid = tid >> 5, lane = tid & 31;
    int grp = lane >> 2, thr = lane & 3;
    int wrow = wid * 16;

    // A staging geometry: thread covers row r = tid>>1, floats [fbase, fbase+16)
    int r = tid >> 1;
    int gr = row0 + r;
    int fbase = (tid & 1) * 16;
    const float* arow_ptr = repre + (size_t)gr * DIM;

    float acc[8][4];
#pragma unroll
    for (int j = 0; j < 8; j++)
#pragma unroll
        for (int q = 0; q < 4; q++) acc[j][q] = 0.f;

    unsigned aAhi = (unsigned)__cvta_generic_to_shared(sAhi);
    unsigned aAlo = (unsigned)__cvta_generic_to_shared(sAlo);
    unsigned aBhi = (unsigned)__cvta_generic_to_shared(sBhi);
    unsigned aBlo = (unsigned)__cvta_generic_to_shared(sBlo);
    int arow = wrow + (lane & 15);
    int acolsel = (lane >> 4) << 3;
    int brow = lane & 7;
    int bcolsel = lane & 8;

    // B staging geometry
    int bn = tid >> 2;
    int bk = (tid & 3) * 8;

    float2 buf[8];          // prefetch buffer for A chunk

    // ---- prefetch chunk 0 ----
#pragma unroll
    for (int i = 0; i < 8; i++) {
        int kg = 0 + fbase + i * 2;
        float2 v = make_float2(0.f, 0.f);
        if (gr < NROWS && kg + 1 < DIM) v = *(const float2*)(arow_ptr + kg);
        buf[i] = v;
    }

    for (int c = 0; c < NCHUNK; c++) {
        int k0 = c * KC;
        // ---- stage A from regs (convert to bf16 hi/lo), stage B ----
        {
            __nv_bfloat16* dhi = sAhi + r * APITCH + fbase;
            __nv_bfloat16* dlo = sAlo + r * APITCH + fbase;
#pragma unroll
            for (int i = 0; i < 8; i++) {
                float2 v = buf[i];
                __nv_bfloat16 hx = __float2bfloat16(v.x);
                __nv_bfloat16 hy = __float2bfloat16(v.y);
                *(__nv_bfloat162*)(dhi + i * 2) = __nv_bfloat162(hx, hy);
                *(__nv_bfloat162*)(dlo + i * 2) =
                    __nv_bfloat162(__float2bfloat16(v.x - __bfloat162float(hx)),
                                   __float2bfloat16(v.y - __bfloat162float(hy)));
            }
            *(uint4*)(sBhi + bn * BPITCH + bk) = *(const uint4*)(g_Bhi + bn * KPAD + k0 + bk);
            *(uint4*)(sBlo + bn * BPITCH + bk) = *(const uint4*)(g_Blo + bn * KPAD + k0 + bk);
        }

        // ---- prefetch chunk c+1 into regs (lands during compute) ----
        if (c + 1 < NCHUNK) {
            int kbase = (c + 1) * KC + fbase;
#pragma unroll
            for (int i = 0; i < 8; i++) {
                int kg = kbase + i * 2;
                float2 v = make_float2(0.f, 0.f);
                if (gr < NROWS) {
                    if (kg + 1 < DIM) v = *(const float2*)(arow_ptr + kg);
                    else if (kg < DIM) v.x = arow_ptr[kg];
                }
                buf[i] = v;
            }
        }
        __syncthreads();

        // ---- compute: 2 k16-steps ----
#pragma unroll
        for (int ks = 0; ks < KC; ks += 16) {
            unsigned ahi[4], alo[4];
            unsigned aoff = (unsigned)((arow * APITCH + ks + acolsel) * 2);
            ldsm4(ahi, aAhi + aoff);
            ldsm4(alo, aAlo + aoff);
#pragma unroll
            for (int j = 0; j < 8; j++) {
                unsigned bhi[2], blo[2];
                unsigned boff = (unsigned)(((j * 8 + brow) * BPITCH + ks + bcolsel) * 2);
                ldsm2(bhi, aBhi + boff);
                ldsm2(blo, aBlo + boff);
                mma_bf16(acc[j], ahi, bhi);
                mma_bf16(acc[j], ahi, blo);
                mma_bf16(acc[j], alo, bhi);
            }
        }
        __syncthreads();
    }

    // ---- epilogue ----
    int r1 = row0 + wrow + grp;
    int r2 = r1 + 8;
#pragma unroll
    for (int j = 0; j < 8; j++) {
        int col = j * 8 + thr * 2;
        if (r1 < NROWS)
            *(float2*)&g_P[(size_t)r1 * NPAD + col] = make_float2(acc[j][0], acc[j][1]);
        if (r2 < NROWS)
            *(float2*)&g_P[(size_t)r2 * NPAD + col] = make_float2(acc[j][2], acc[j][3]);
    }
}

// ---------------- K2: per-bag softmax + combine over P ---------------------
__global__ __launch_bounds__(256) void k_bags(const int* __restrict__ scope,
                                              const int* __restrict__ labels,
                                              const float* __restrict__ bias,
                                              float* __restrict__ out) {
    __shared__ float wbuf[8][WCAP];
    int wid = threadIdx.x >> 5, lane = threadIdx.x & 31;
    int bag = blockIdx.x * 8 + wid;
    if (bag >= NBAGS) return;
    int s = scope[2 * bag];
    int e = scope[2 * bag + 1];
    int c = e - s;
    float* w = (c <= WCAP) ? wbuf[wid] : (g_wglob + s);

    // logits (gather) + max
    float m = -FLT_MAX;
    for (int i = lane; i < c; i += 32) {
        int gi = s + i;
        float lg = g_P[(size_t)gi * NPAD + labels[gi]];
        w[i] = lg;
        m = fmaxf(m, lg);
    }
#pragma unroll
    for (int o = 16; o; o >>= 1) m = fmaxf(m, __shfl_xor_sync(0xffffffffu, m, o));

    // exp + sum
    float sum = 0.f;
    for (int i = lane; i < c; i += 32) {
        float ev = __expf(w[i] - m);
        w[i] = ev;
        sum += ev;
    }
#pragma unroll
    for (int o = 16; o; o >>= 1) sum += __shfl_xor_sync(0xffffffffu, sum, o);
    float inv = 1.f / sum;
    __syncwarp();

    // combine: lane covers cols [2*lane, 2*lane+1] via float2
    int col = lane * 2;
    float2 o2 = make_float2(0.f, 0.f);
    const float* pbase = g_P + (size_t)s * NPAD + col;
#pragma unroll 4
    for (int i = 0; i < c; i++) {
        float wi = w[i] * inv;
        float2 p2 = *(const float2*)(pbase + (size_t)i * NPAD);
        o2.x = fmaf(wi, p2.x, o2.x);
        o2.y = fmaf(wi, p2.y, o2.y);
    }
    if (col < NREL)     out[(size_t)bag * NREL + col]     = o2.x + bias[col];
    if (col + 1 < NREL) out[(size_t)bag * NREL + col + 1] = o2.y + bias[col + 1];
}

// ---------------- launch ----------------
extern "C" void kernel_launch(void* const* d_in, const int* in_sizes, int n_in,
                              void* d_out, int out_size) {
    const float* repre  = (const float*)d_in[0];   // [N, D]
    const float* rel    = (const float*)d_in[1];   // [R, D]
    const float* bias   = (const float*)d_in[2];   // [R]
    const int* scope    = (const int*)d_in[3];     // [NBAGS, 2] int32
    const int* labels   = (const int*)d_in[4];     // [N]        int32
    float* out = (float*)d_out;                    // [NBAGS, R]

    (void)in_sizes; (void)n_in; (void)out_size;

    k_prep<<<(NPAD * KPAD + 255) / 256, 256>>>(rel);
    k_pgemm<<<(NROWS + BM - 1) / BM, 256>>>(repre);
    k_bags<<<(NBAGS + 7) / 8, 256>>>(scope, labels, bias, out);
}

// round 6
// speedup vs baseline: 1.1460x; 1.1460x over previous
#include <cuda_runtime.h>
#include <cuda_bf16.h>
#include <math.h>
#include <float.h>

#define NROWS 200000
#define NBAGS 25000
#define DIM   690
#define NREL  53
#define KPAD  704
#define NPAD  64
#define BM    128
#define KC    32
#define NCHUNK 22          // KPAD / KC
#define PF    36           // fp32 A stage pitch (floats) -> conflict-friendly
#define BPITCH 40          // bf16 B pitch (80B rows, LDSM conflict-free)
#define NSTAGE 3
#define A_STAGE_BYTES (BM * PF * 4)            // 18432
#define B_HALF_BYTES  (NPAD * BPITCH * 2)      // 5120
#define B_STAGE_BYTES (2 * B_HALF_BYTES)       // 10240 (hi then lo)
#define SMEM_B_OFF    (NSTAGE * A_STAGE_BYTES) // 55296
#define SMEM_TOTAL    (SMEM_B_OFF + NSTAGE * B_STAGE_BYTES)  // 86016
#define WCAP  128

// ---------------- scratch (device globals: allocation-free) ----------------
__device__ __align__(16) float g_P[(size_t)NROWS * NPAD];       // 51.2 MB
__device__ __align__(16) __nv_bfloat16 g_Bhi[NPAD * KPAD];
__device__ __align__(16) __nv_bfloat16 g_Blo[NPAD * KPAD];
__device__ float g_wglob[NROWS];

// ---------------- K0: build bf16 hi/lo B = rel (padded, [n][k]) ------------
__global__ void k_prep(const float* __restrict__ rel) {
    int idx = blockIdx.x * blockDim.x + threadIdx.x;
    if (idx >= NPAD * KPAD) return;
    int n = idx / KPAD, k = idx % KPAD;
    float v = (n < NREL && k < DIM) ? rel[n * DIM + k] : 0.f;
    __nv_bfloat16 hi = __float2bfloat16(v);
    g_Bhi[idx] = hi;
    g_Blo[idx] = __float2bfloat16(v - __bfloat162float(hi));
}

// ---------------- PTX helpers ----------------
__device__ __forceinline__ void mma_bf16(float* c, const unsigned* a, const unsigned* b) {
    asm volatile(
        "mma.sync.aligned.m16n8k16.row.col.f32.bf16.bf16.f32 "
        "{%0,%1,%2,%3}, {%4,%5,%6,%7}, {%8,%9}, {%0,%1,%2,%3};"
        : "+f"(c[0]), "+f"(c[1]), "+f"(c[2]), "+f"(c[3])
        : "r"(a[0]), "r"(a[1]), "r"(a[2]), "r"(a[3]), "r"(b[0]), "r"(b[1]));
}
__device__ __forceinline__ void ldsm2(unsigned* r, unsigned addr) {
    asm volatile("ldmatrix.sync.aligned.m8n8.x2.shared.b16 {%0,%1}, [%2];"
                 : "=r"(r[0]), "=r"(r[1]) : "r"(addr));
}
__device__ __forceinline__ void cp8(unsigned dst, const void* src, int bytes) {
    asm volatile("cp.async.ca.shared.global [%0], [%1], 8, %2;"
                 :: "r"(dst), "l"(src), "r"(bytes));
}
__device__ __forceinline__ void cp16(unsigned dst, const void* src) {
    asm volatile("cp.async.cg.shared.global [%0], [%1], 16;"
                 :: "r"(dst), "l"(src));
}
__device__ __forceinline__ void cp_commit() {
    asm volatile("cp.async.commit_group;" ::: "memory");
}
__device__ __forceinline__ void cp_wait1() {
    asm volatile("cp.async.wait_group 1;" ::: "memory");
}

// ---------------- K1: P = repre @ rel^T, pipelined hi/lo bf16 MMA ----------
__global__ __launch_bounds__(256) void k_pgemm(const float* __restrict__ repre) {
    extern __shared__ __align__(16) char smem[];
    unsigned sbase = (unsigned)__cvta_generic_to_shared(smem);
    float* sF = (float*)smem;

    int row0 = blockIdx.x * BM;
    int tid = threadIdx.x, wid = tid >> 5, lane = tid & 31;

    // ---- A cp geometry: thread covers row ar, 8 slots of 2 floats (8B) ----
    int ar  = tid >> 1;
    int asb = (tid & 1) * 8;           // slot base (slots of 2 floats; 16 slots/row)
    int gr  = row0 + ar;
    bool arow_ok = gr < NROWS;
    const float* asrc_row = repre + (size_t)(arow_ok ? gr : (NROWS - 1)) * DIM;
    unsigned adst_row = sbase + (unsigned)(ar * PF * 4);

    // ---- B cp geometry: thread covers one 16B slot of hi and of lo ----
    int bn = tid >> 2, bs = tid & 3;   // row 0..63, slot 0..3 (8 bf16 each)
    unsigned bdst = sbase + SMEM_B_OFF + (unsigned)((bn * BPITCH + bs * 8) * 2);

    // ---- compute geometry ----
    int wrow = wid * 16;
    int g = lane >> 2, th = lane & 3;
    int brow = lane & 7, bcolsel = lane & 8;
    int grp = g, thr = th;

    float acc[8][4];
#pragma unroll
    for (int j = 0; j < 8; j++)
#pragma unroll
        for (int q = 0; q < 4; q++) acc[j][q] = 0.f;

    // ---- issue one stage's cp.asyncs ----
    auto issue = [&](int cs) {
        int st = cs % NSTAGE;
        int k0 = cs * KC;
        unsigned da = adst_row + (unsigned)(st * A_STAGE_BYTES) + (unsigned)(asb * 8);
#pragma unroll
        for (int i = 0; i < 8; i++) {
            int kf = k0 + (asb + i) * 2;
            int bytes = arow_ok ? max(0, min(8, (DIM - kf) * 4)) : 0;
            const float* sp = asrc_row + (bytes > 0 ? kf : 0);
            cp8(da + i * 8, sp, bytes);
        }
        unsigned db = bdst + (unsigned)(st * B_STAGE_BYTES);
        int boffg = bn * KPAD + k0 + bs * 8;
        cp16(db, g_Bhi + boffg);
        cp16(db + B_HALF_BYTES, g_Blo + boffg);
    };

    // ---- prologue: fill NSTAGE-1 stages ----
    issue(0); cp_commit();
    issue(1); cp_commit();

    for (int c = 0; c < NCHUNK; c++) {
        cp_wait1();
        __syncthreads();
        int st = c % NSTAGE;
        const float* A = sF + st * (BM * PF);
        unsigned sBst = sbase + SMEM_B_OFF + (unsigned)(st * B_STAGE_BYTES);

        // ---- build A hi/lo fragments in registers (both k16 steps) ----
        unsigned ahi[2][4], alo[2][4];
#pragma unroll
        for (int ks2 = 0; ks2 < 2; ks2++) {
#pragma unroll
            for (int q = 0; q < 4; q++) {
                int r   = wrow + g + (q & 1) * 8;
                int col = ks2 * 16 + th * 2 + (q >> 1) * 8;
                float2 v = *(const float2*)(A + r * PF + col);
                unsigned ux = __float_as_uint(v.x), uy = __float_as_uint(v.y);
                unsigned hi;
                asm("prmt.b32 %0, %1, %2, 0x7632;" : "=r"(hi) : "r"(ux), "r"(uy));
                float hx = __uint_as_float(ux & 0xffff0000u);
                float hy = __uint_as_float(uy & 0xffff0000u);
                float lx = v.x - hx, ly = v.y - hy;
                unsigned lo;
                asm("cvt.rn.bf16x2.f32 %0, %1, %2;" : "=r"(lo) : "f"(ly), "f"(lx));
                ahi[ks2][q] = hi; alo[ks2][q] = lo;
            }
        }

        // ---- MMA over 8 n-tiles x 2 k-steps x 3 terms ----
#pragma unroll
        for (int j = 0; j < 8; j++) {
            unsigned bb = sBst + (unsigned)(((j * 8 + brow) * BPITCH + bcolsel) * 2);
#pragma unroll
            for (int ks2 = 0; ks2 < 2; ks2++) {
                unsigned bhi[2], blo[2];
                ldsm2(bhi, bb + ks2 * 32);
                ldsm2(blo, bb + B_HALF_BYTES + ks2 * 32);
                mma_bf16(acc[j], ahi[ks2], bhi);
                mma_bf16(acc[j], alo[ks2], bhi);
                mma_bf16(acc[j], ahi[ks2], blo);
            }
        }
        __syncthreads();
        if (c + NSTAGE - 1 < NCHUNK) issue(c + NSTAGE - 1);
        cp_commit();
    }

    // ---- epilogue: write P ----
    int r1 = row0 + wrow + grp;
    int r2 = r1 + 8;
#pragma unroll
    for (int j = 0; j < 8; j++) {
        int col = j * 8 + thr * 2;
        if (r1 < NROWS)
            *(float2*)&g_P[(size_t)r1 * NPAD + col] = make_float2(acc[j][0], acc[j][1]);
        if (r2 < NROWS)
            *(float2*)&g_P[(size_t)r2 * NPAD + col] = make_float2(acc[j][2], acc[j][3]);
    }
}

// ---------------- K2: per-bag softmax + combine over P ---------------------
__global__ __launch_bounds__(256) void k_bags(const int* __restrict__ scope,
                                              const int* __restrict__ labels,
                                              const float* __restrict__ bias,
                                              float* __restrict__ out) {
    __shared__ float wbuf[8][WCAP];
    int wid = threadIdx.x >> 5, lane = threadIdx.x & 31;
    int bag = blockIdx.x * 8 + wid;
    if (bag >= NBAGS) return;
    int s = scope[2 * bag];
    int e = scope[2 * bag + 1];
    int c = e - s;
    float* w = (c <= WCAP) ? wbuf[wid] : (g_wglob + s);

    float m = -FLT_MAX;
    for (int i = lane; i < c; i += 32) {
        int gi = s + i;
        float lg = g_P[(size_t)gi * NPAD + labels[gi]];
        w[i] = lg;
        m = fmaxf(m, lg);
    }
#pragma unroll
    for (int o = 16; o; o >>= 1) m = fmaxf(m, __shfl_xor_sync(0xffffffffu, m, o));

    float sum = 0.f;
    for (int i = lane; i < c; i += 32) {
        float ev = __expf(w[i] - m);
        w[i] = ev;
        sum += ev;
    }
#pragma unroll
    for (int o = 16; o; o >>= 1) sum += __shfl_xor_sync(0xffffffffu, sum, o);
    float inv = 1.f / sum;
    __syncwarp();

    int col = lane * 2;
    float2 o2 = make_float2(0.f, 0.f);
    const float* pbase = g_P + (size_t)s * NPAD + col;
#pragma unroll 4
    for (int i = 0; i < c; i++) {
        float wi = w[i] * inv;
        float2 p2 = *(const float2*)(pbase + (size_t)i * NPAD);
        o2.x = fmaf(wi, p2.x, o2.x);
        o2.y = fmaf(wi, p2.y, o2.y);
    }
    if (col < NREL)     out[(size_t)bag * NREL + col]     = o2.x + bias[col];
    if (col + 1 < NREL) out[(size_t)bag * NREL + col + 1] = o2.y + bias[col + 1];
}

// ---------------- launch ----------------
extern "C" void kernel_launch(void* const* d_in, const int* in_sizes, int n_in,
                              void* d_out, int out_size) {
    const float* repre  = (const float*)d_in[0];   // [N, D]
    const float* rel    = (const float*)d_in[1];   // [R, D]
    const float* bias   = (const float*)d_in[2];   // [R]
    const int* scope    = (const int*)d_in[3];     // [NBAGS, 2] int32
    const int* labels   = (const int*)d_in[4];     // [N]        int32
    float* out = (float*)d_out;                    // [NBAGS, R]

    (void)in_sizes; (void)n_in; (void)out_size;

    cudaFuncSetAttribute(k_pgemm, cudaFuncAttributeMaxDynamicSharedMemorySize,
                         SMEM_TOTAL);

    k_prep<<<(NPAD * KPAD + 255) / 256, 256>>>(rel);
    k_pgemm<<<(NROWS + BM - 1) / BM, 256, SMEM_TOTAL>>>(repre);
    k_bags<<<(NBAGS + 7) / 8, 256>>>(scope, labels, bias, out);
}